// round 14
// baseline (speedup 1.0000x reference)
#include <cuda_runtime.h>
#include <cuda_bf16.h>
#include <math.h>
#include <stdint.h>

#define LDIM 96
#define FDIM 192
#define TILE_R 64
#define NTHREADS 512     // 16 warps = 4 m-blocks x 4 n-quarters

// smem byte offsets (16B aligned); pitches chosen conflict-free:
//  P96 = 208 B  (k=96 arrays), P192 = 400 B (k=192 arrays)
#define P96   208
#define P192  400
#define OFF_B1H 0                      // M1 hi: 192 n x 96 k bf16 (39,936)
#define OFF_B1L 39936
#define OFF_B2H 79872                  // W2^T hi: 96 n x 192 k bf16 (38,400)
#define OFF_B2L 118272
#define OFF_XH  156672                 // X hi: 64 x 96 bf16 (13,312)   [aliases H]
#define OFF_XL  169984
#define OFF_HH  156672                 // H hi: 64 x 192 bf16 (25,600)
#define OFF_HL  182272
#define OFF_S   207872                 // 4 x 64 f32 (1,024)
#define OFF_Q   208896                 // 4 x 64 f32 (1,024)
#define OFF_GAM 209920                 // 96 f32
#define OFF_BET 210304                 // 96 f32
#define SMEM_BYTES 210688

// Folded DCT * W1 (96 x 192), fp64 accumulation, recomputed every launch.
__device__ float g_M1[LDIM * FDIM];

__global__ void precompute_m1_kernel(const float* __restrict__ W1) {
    int n = blockIdx.x;
    int j = threadIdx.x;
    double base = 3.14159265358979323846 * (2.0 * (double)n + 1.0) / (2.0 * (double)LDIM);
    double acc = 0.0;
    for (int f = 0; f < LDIM; ++f)
        acc += 2.0 * cos(base * (double)f) * (double)W1[f * FDIM + j];
    g_M1[n * FDIM + j] = (float)acc;
}

__device__ __forceinline__ void mma_bf16(float* c, uint32_t a0, uint32_t a1,
                                         uint32_t a2, uint32_t a3,
                                         uint32_t b0, uint32_t b1) {
    asm volatile(
        "mma.sync.aligned.m16n8k16.row.col.f32.bf16.bf16.f32 "
        "{%0,%1,%2,%3}, {%4,%5,%6,%7}, {%8,%9}, {%0,%1,%2,%3};"
        : "+f"(c[0]), "+f"(c[1]), "+f"(c[2]), "+f"(c[3])
        : "r"(a0), "r"(a1), "r"(a2), "r"(a3), "r"(b0), "r"(b1));
}

// split v -> bf16 hi + bf16 lo (residual)
__device__ __forceinline__ void split1(float v, uint16_t& h, uint16_t& l) {
    __nv_bfloat16 hb = __float2bfloat16(v);
    __nv_bfloat16 lb = __float2bfloat16(v - __bfloat162float(hb));
    h = __bfloat16_as_ushort(hb);
    l = __bfloat16_as_ushort(lb);
}
__device__ __forceinline__ uint32_t pack2(uint16_t lo, uint16_t hi) {
    return (uint32_t)lo | ((uint32_t)hi << 16);
}

__global__ void __launch_bounds__(NTHREADS, 1)
fused_mma_kernel(const float* __restrict__ x,
                 const float* __restrict__ W2,
                 const float* __restrict__ gamma,
                 const float* __restrict__ beta,
                 float* __restrict__ out,
                 int ntiles)
{
    extern __shared__ char sm[];
    float* S   = (float*)(sm + OFF_S);
    float* Q   = (float*)(sm + OFF_Q);
    float* GAM = (float*)(sm + OFF_GAM);
    float* BET = (float*)(sm + OFF_BET);

    const int tid  = threadIdx.x;
    const int lane = tid & 31;
    const int wid  = tid >> 5;         // 0..15
    const int mi   = wid & 3;          // m16 block 0..3
    const int nq   = wid >> 2;         // n-quarter 0..3
    const int g    = lane >> 2;        // 0..7
    const int t    = lane & 3;         // 0..3
    const int M0   = mi * 16;

    // ---- one-time weight prep: bf16 hi/lo, conflict-free pitches ----
    for (int i = tid; i < LDIM * FDIM; i += NTHREADS) {      // B1[n][k] = M1[k][n]
        int k = i / FDIM, n = i - k * FDIM;
        uint16_t h, l; split1(g_M1[i], h, l);
        *(uint16_t*)(sm + OFF_B1H + n * P96 + k * 2) = h;
        *(uint16_t*)(sm + OFF_B1L + n * P96 + k * 2) = l;
    }
    for (int i = tid; i < FDIM * LDIM; i += NTHREADS) {      // B2[n][k] = W2[k][n]
        int k = i / LDIM, n = i - k * LDIM;
        uint16_t h, l; split1(W2[i], h, l);
        *(uint16_t*)(sm + OFF_B2H + n * P192 + k * 2) = h;
        *(uint16_t*)(sm + OFF_B2L + n * P192 + k * 2) = l;
    }
    if (tid < 96) { GAM[tid] = gamma[tid]; BET[tid] = beta[tid]; }
    __syncthreads();

    for (int tile = blockIdx.x; tile < ntiles; tile += gridDim.x) {
        const size_t rowbase = (size_t)tile * TILE_R;

        // ---- 1) stage X (64x96 fp32 -> bf16 hi/lo in smem) ----
        {
            const float4* xg = (const float4*)(x + rowbase * LDIM);
            #pragma unroll
            for (int it = 0; it < 3; ++it) {
                int i4 = tid + it * NTHREADS;
                float4 v = xg[i4];
                int e = i4 * 4, r = e / LDIM, c = e - LDIM * r;   // c % 4 == 0
                uint16_t hx, lx, hy, ly, hz, lz, hw, lw;
                split1(v.x, hx, lx); split1(v.y, hy, ly);
                split1(v.z, hz, lz); split1(v.w, hw, lw);
                *(uint32_t*)(sm + OFF_XH + r * P96 + c * 2)     = pack2(hx, hy);
                *(uint32_t*)(sm + OFF_XH + r * P96 + c * 2 + 4) = pack2(hz, hw);
                *(uint32_t*)(sm + OFF_XL + r * P96 + c * 2)     = pack2(lx, ly);
                *(uint32_t*)(sm + OFF_XL + r * P96 + c * 2 + 4) = pack2(lz, lw);
            }
        }
        __syncthreads();

        // ---- 2) GEMM1: D1(64x192) = X @ M1, split hh+hl+lh; 6 j per warp ----
        float acc1[6][4];
        #pragma unroll
        for (int j = 0; j < 6; ++j)
            #pragma unroll
            for (int p = 0; p < 4; ++p) acc1[j][p] = 0.f;

        #pragma unroll
        for (int ks = 0; ks < 6; ++ks) {
            int abyte = (M0 + g) * P96 + ks * 32 + 4 * t;
            uint32_t ah0 = *(const uint32_t*)(sm + OFF_XH + abyte);
            uint32_t ah1 = *(const uint32_t*)(sm + OFF_XH + abyte + 8 * P96);
            uint32_t ah2 = *(const uint32_t*)(sm + OFF_XH + abyte + 16);
            uint32_t ah3 = *(const uint32_t*)(sm + OFF_XH + abyte + 8 * P96 + 16);
            uint32_t al0 = *(const uint32_t*)(sm + OFF_XL + abyte);
            uint32_t al1 = *(const uint32_t*)(sm + OFF_XL + abyte + 8 * P96);
            uint32_t al2 = *(const uint32_t*)(sm + OFF_XL + abyte + 16);
            uint32_t al3 = *(const uint32_t*)(sm + OFF_XL + abyte + 8 * P96 + 16);
            #pragma unroll
            for (int j = 0; j < 6; ++j) {
                int bbyte = ((nq * 6 + j) * 8 + g) * P96 + ks * 32 + 4 * t;
                uint32_t bh0 = *(const uint32_t*)(sm + OFF_B1H + bbyte);
                uint32_t bh1 = *(const uint32_t*)(sm + OFF_B1H + bbyte + 16);
                uint32_t bl0 = *(const uint32_t*)(sm + OFF_B1L + bbyte);
                uint32_t bl1 = *(const uint32_t*)(sm + OFF_B1L + bbyte + 16);
                mma_bf16(acc1[j], ah0, ah1, ah2, ah3, bh0, bh1);
                mma_bf16(acc1[j], ah0, ah1, ah2, ah3, bl0, bl1);
                mma_bf16(acc1[j], al0, al1, al2, al3, bh0, bh1);
            }
        }
        __syncthreads();   // X reads done -> region becomes H

        // ---- 3) relu + split -> H hi/lo in smem ----
        #pragma unroll
        for (int j = 0; j < 6; ++j) {
            int N0 = (nq * 6 + j) * 8;
            float c0 = fmaxf(acc1[j][0], 0.f), c1 = fmaxf(acc1[j][1], 0.f);
            float c2 = fmaxf(acc1[j][2], 0.f), c3 = fmaxf(acc1[j][3], 0.f);
            uint16_t h0, l0, h1, l1; split1(c0, h0, l0); split1(c1, h1, l1);
            uint16_t h2, l2, h3, l3; split1(c2, h2, l2); split1(c3, h3, l3);
            int b0 = (M0 + g) * P192 + (N0 + 2 * t) * 2;
            int b1 = (M0 + g + 8) * P192 + (N0 + 2 * t) * 2;
            *(uint32_t*)(sm + OFF_HH + b0) = pack2(h0, h1);
            *(uint32_t*)(sm + OFF_HL + b0) = pack2(l0, l1);
            *(uint32_t*)(sm + OFF_HH + b1) = pack2(h2, h3);
            *(uint32_t*)(sm + OFF_HL + b1) = pack2(l2, l3);
        }
        __syncthreads();

        // ---- 4) GEMM2: D2(64x96) = H @ W2, split hh+hl+lh; 3 j per warp ----
        float acc2[3][4];
        #pragma unroll
        for (int j = 0; j < 3; ++j)
            #pragma unroll
            for (int p = 0; p < 4; ++p) acc2[j][p] = 0.f;

        #pragma unroll
        for (int ks = 0; ks < 12; ++ks) {
            int abyte = (M0 + g) * P192 + ks * 32 + 4 * t;
            uint32_t ah0 = *(const uint32_t*)(sm + OFF_HH + abyte);
            uint32_t ah1 = *(const uint32_t*)(sm + OFF_HH + abyte + 8 * P192);
            uint32_t ah2 = *(const uint32_t*)(sm + OFF_HH + abyte + 16);
            uint32_t ah3 = *(const uint32_t*)(sm + OFF_HH + abyte + 8 * P192 + 16);
            uint32_t al0 = *(const uint32_t*)(sm + OFF_HL + abyte);
            uint32_t al1 = *(const uint32_t*)(sm + OFF_HL + abyte + 8 * P192);
            uint32_t al2 = *(const uint32_t*)(sm + OFF_HL + abyte + 16);
            uint32_t al3 = *(const uint32_t*)(sm + OFF_HL + abyte + 8 * P192 + 16);
            #pragma unroll
            for (int j = 0; j < 3; ++j) {
                int bbyte = ((nq * 3 + j) * 8 + g) * P192 + ks * 32 + 4 * t;
                uint32_t bh0 = *(const uint32_t*)(sm + OFF_B2H + bbyte);
                uint32_t bh1 = *(const uint32_t*)(sm + OFF_B2H + bbyte + 16);
                uint32_t bl0 = *(const uint32_t*)(sm + OFF_B2L + bbyte);
                uint32_t bl1 = *(const uint32_t*)(sm + OFF_B2L + bbyte + 16);
                mma_bf16(acc2[j], ah0, ah1, ah2, ah3, bh0, bh1);
                mma_bf16(acc2[j], ah0, ah1, ah2, ah3, bl0, bl1);
                mma_bf16(acc2[j], al0, al1, al2, al3, bh0, bh1);
            }
        }

        // ---- 5) sigmoid + LayerNorm + x*lr ----
        {
            const int r0 = M0 + g, r1 = M0 + g + 8;
            float v[3][4];
            float p0 = 0.f, p1 = 0.f;
            #pragma unroll
            for (int j = 0; j < 3; ++j) {
                #pragma unroll
                for (int p = 0; p < 4; ++p)
                    v[j][p] = __fdividef(1.f, 1.f + __expf(-acc2[j][p]));
                p0 += v[j][0] + v[j][1];
                p1 += v[j][2] + v[j][3];
            }
            p0 += __shfl_xor_sync(0xffffffffu, p0, 1);
            p0 += __shfl_xor_sync(0xffffffffu, p0, 2);
            p1 += __shfl_xor_sync(0xffffffffu, p1, 1);
            p1 += __shfl_xor_sync(0xffffffffu, p1, 2);
            if (t == 0) { S[nq * 64 + r0] = p0; S[nq * 64 + r1] = p1; }
            __syncthreads();
            float mu0 = (S[r0] + S[64 + r0] + S[128 + r0] + S[192 + r0]) * (1.f / 96.f);
            float mu1 = (S[r1] + S[64 + r1] + S[128 + r1] + S[192 + r1]) * (1.f / 96.f);

            float q0 = 0.f, q1 = 0.f;
            #pragma unroll
            for (int j = 0; j < 3; ++j) {
                float d0 = v[j][0] - mu0, d1 = v[j][1] - mu0;
                float d2 = v[j][2] - mu1, d3 = v[j][3] - mu1;
                q0 += d0 * d0 + d1 * d1;
                q1 += d2 * d2 + d3 * d3;
            }
            q0 += __shfl_xor_sync(0xffffffffu, q0, 1);
            q0 += __shfl_xor_sync(0xffffffffu, q0, 2);
            q1 += __shfl_xor_sync(0xffffffffu, q1, 1);
            q1 += __shfl_xor_sync(0xffffffffu, q1, 2);
            if (t == 0) { Q[nq * 64 + r0] = q0; Q[nq * 64 + r1] = q1; }
            __syncthreads();
            float inv0 = rsqrtf((Q[r0] + Q[64 + r0] + Q[128 + r0] + Q[192 + r0]) * (1.f / 96.f) + 1e-6f);
            float inv1 = rsqrtf((Q[r1] + Q[64 + r1] + Q[128 + r1] + Q[192 + r1]) * (1.f / 96.f) + 1e-6f);

            #pragma unroll
            for (int j = 0; j < 3; ++j) {
                int col = (nq * 3 + j) * 8 + 2 * t;
                float2 gmv = *(const float2*)&GAM[col];
                float2 btv = *(const float2*)&BET[col];
                float2 xv0 = *(const float2*)(x + (rowbase + r0) * LDIM + col);
                float2 xv1 = *(const float2*)(x + (rowbase + r1) * LDIM + col);
                float2 o0, o1;
                o0.x = xv0.x * ((v[j][0] - mu0) * inv0 * gmv.x + btv.x);
                o0.y = xv0.y * ((v[j][1] - mu0) * inv0 * gmv.y + btv.y);
                o1.x = xv1.x * ((v[j][2] - mu1) * inv1 * gmv.x + btv.x);
                o1.y = xv1.y * ((v[j][3] - mu1) * inv1 * gmv.y + btv.y);
                *(float2*)(out + (rowbase + r0) * LDIM + col) = o0;
                *(float2*)(out + (rowbase + r1) * LDIM + col) = o1;
            }
        }
        __syncthreads();   // H reads done before next tile's X staging
    }
}

extern "C" void kernel_launch(void* const* d_in, const int* in_sizes, int n_in,
                              void* d_out, int out_size) {
    const float* x     = (const float*)d_in[0];
    const float* W1    = (const float*)d_in[1];
    const float* W2    = (const float*)d_in[2];
    const float* gamma = (const float*)d_in[3];
    const float* beta  = (const float*)d_in[4];
    float* out = (float*)d_out;

    int rows   = in_sizes[0] / LDIM;     // 786432
    int ntiles = rows / TILE_R;          // 12288

    precompute_m1_kernel<<<LDIM, FDIM>>>(W1);

    cudaFuncSetAttribute(fused_mma_kernel,
                         cudaFuncAttributeMaxDynamicSharedMemorySize, SMEM_BYTES);

    int nsm = 148;
    cudaDeviceGetAttribute(&nsm, cudaDevAttrMultiProcessorCount, 0);
    int grid = nsm < ntiles ? nsm : ntiles;

    fused_mma_kernel<<<grid, NTHREADS, SMEM_BYTES>>>(x, W2, gamma, beta, out, ntiles);
}

// round 15
// speedup vs baseline: 1.5251x; 1.5251x over previous
#include <cuda_runtime.h>
#include <cuda_fp16.h>
#include <math.h>
#include <stdint.h>

#define LDIM 96
#define FDIM 192
#define TILE_R 64
#define NTHREADS 256     // 8 warps = 4 m-blocks x 2 n-halves

// pitches conflict-free: P96 = 208 B (k=96), P192 = 400 B (k=192)
#define P96   208
#define P192  400
#define OFF_B1H 0                      // M1 hi: 192 n x 96 k fp16 (39,936)
#define OFF_B1L 39936
#define OFF_B2H 79872                  // W2^T hi: 96 n x 192 k fp16 (38,400)
#define OFF_B2L 118272
#define OFF_XH  156672                 // X hi: 64 x 96 fp16 (13,312)  [aliases H]
#define OFF_HH  156672                 // H hi: 64 x 192 fp16 (25,600)
#define OFF_S   182272                 // 2 x 64 f32
#define OFF_Q   182784                 // 2 x 64 f32
#define OFF_GAM 183296                 // 96 f32
#define OFF_BET 183680                 // 96 f32
#define SMEM_BYTES 184064

// Folded DCT * W1 (96 x 192), fp64 accumulation, recomputed every launch.
__device__ float g_M1[LDIM * FDIM];

// cos table in smem: 9.2k fp64 cos total instead of 1.77M.
__global__ void precompute_m1_kernel(const float* __restrict__ W1) {
    __shared__ double ct[LDIM];
    int n = blockIdx.x;    // 0..95
    int j = threadIdx.x;   // 0..191
    if (j < LDIM) {
        double base = 3.14159265358979323846 * (2.0 * (double)n + 1.0) / (2.0 * (double)LDIM);
        ct[j] = 2.0 * cos(base * (double)j);
    }
    __syncthreads();
    double acc = 0.0;
    for (int f = 0; f < LDIM; ++f)
        acc += ct[f] * (double)W1[f * FDIM + j];
    g_M1[n * FDIM + j] = (float)acc;
}

__device__ __forceinline__ void mma_f16(float* c, uint32_t a0, uint32_t a1,
                                        uint32_t a2, uint32_t a3,
                                        uint32_t b0, uint32_t b1) {
    asm volatile(
        "mma.sync.aligned.m16n8k16.row.col.f32.f16.f16.f32 "
        "{%0,%1,%2,%3}, {%4,%5,%6,%7}, {%8,%9}, {%0,%1,%2,%3};"
        : "+f"(c[0]), "+f"(c[1]), "+f"(c[2]), "+f"(c[3])
        : "r"(a0), "r"(a1), "r"(a2), "r"(a3), "r"(b0), "r"(b1));
}

// split v -> fp16 hi + fp16 lo (residual); h16 = hi only
__device__ __forceinline__ void split1(float v, uint16_t& h, uint16_t& l) {
    __half hb = __float2half_rn(v);
    __half lb = __float2half_rn(v - __half2float(hb));
    h = __half_as_ushort(hb);
    l = __half_as_ushort(lb);
}
__device__ __forceinline__ uint16_t h16(float v) {
    return __half_as_ushort(__float2half_rn(v));
}
__device__ __forceinline__ uint32_t pack2(uint16_t lo, uint16_t hi) {
    return (uint32_t)lo | ((uint32_t)hi << 16);
}

__global__ void __launch_bounds__(NTHREADS, 1)
fused_mma_kernel(const float* __restrict__ x,
                 const float* __restrict__ W2,
                 const float* __restrict__ gamma,
                 const float* __restrict__ beta,
                 float* __restrict__ out,
                 int ntiles)
{
    extern __shared__ char sm[];
    float* S   = (float*)(sm + OFF_S);
    float* Q   = (float*)(sm + OFF_Q);
    float* GAM = (float*)(sm + OFF_GAM);
    float* BET = (float*)(sm + OFF_BET);

    const int tid  = threadIdx.x;
    const int lane = tid & 31;
    const int wid  = tid >> 5;         // 0..7
    const int mi   = wid & 3;          // m16 block 0..3
    const int nh   = wid >> 2;         // n-half 0..1
    const int g    = lane >> 2;        // 0..7
    const int t    = lane & 3;         // 0..3
    const int M0   = mi * 16;

    // ---- one-time weight prep: fp16 hi/lo (B near-exact), conflict-free pitches ----
    for (int i = tid; i < LDIM * FDIM; i += NTHREADS) {      // B1[n][k] = M1[k][n]
        int k = i / FDIM, n = i - k * FDIM;
        uint16_t h, l; split1(g_M1[i], h, l);
        *(uint16_t*)(sm + OFF_B1H + n * P96 + k * 2) = h;
        *(uint16_t*)(sm + OFF_B1L + n * P96 + k * 2) = l;
    }
    for (int i = tid; i < FDIM * LDIM; i += NTHREADS) {      // B2[n][k] = W2[k][n]
        int k = i / LDIM, n = i - k * LDIM;
        uint16_t h, l; split1(W2[i], h, l);
        *(uint16_t*)(sm + OFF_B2H + n * P192 + k * 2) = h;
        *(uint16_t*)(sm + OFF_B2L + n * P192 + k * 2) = l;
    }
    if (tid < 96) { GAM[tid] = gamma[tid]; BET[tid] = beta[tid]; }
    __syncthreads();

    for (int tile = blockIdx.x; tile < ntiles; tile += gridDim.x) {
        const size_t rowbase = (size_t)tile * TILE_R;

        // ---- 1) stage X (64x96 fp32 -> fp16 hi only in smem) ----
        {
            const float4* xg = (const float4*)(x + rowbase * LDIM);
            #pragma unroll
            for (int it = 0; it < 6; ++it) {
                int i4 = tid + it * NTHREADS;
                float4 v = xg[i4];
                int e = i4 * 4, r = e / LDIM, c = e - LDIM * r;   // c % 4 == 0
                *(uint32_t*)(sm + OFF_XH + r * P96 + c * 2)     = pack2(h16(v.x), h16(v.y));
                *(uint32_t*)(sm + OFF_XH + r * P96 + c * 2 + 4) = pack2(h16(v.z), h16(v.w));
            }
        }
        __syncthreads();

        // ---- 2) GEMM1: D1(64x192) = Xh @ (B1h + B1l), 2 MMA/term ----
        float acc1[12][4];
        #pragma unroll
        for (int j = 0; j < 12; ++j)
            #pragma unroll
            for (int p = 0; p < 4; ++p) acc1[j][p] = 0.f;

        #pragma unroll
        for (int ks = 0; ks < 6; ++ks) {
            int abyte = (M0 + g) * P96 + ks * 32 + 4 * t;
            uint32_t ah0 = *(const uint32_t*)(sm + OFF_XH + abyte);
            uint32_t ah1 = *(const uint32_t*)(sm + OFF_XH + abyte + 8 * P96);
            uint32_t ah2 = *(const uint32_t*)(sm + OFF_XH + abyte + 16);
            uint32_t ah3 = *(const uint32_t*)(sm + OFF_XH + abyte + 8 * P96 + 16);
            #pragma unroll
            for (int j = 0; j < 12; ++j) {
                int bbyte = ((nh * 12 + j) * 8 + g) * P96 + ks * 32 + 4 * t;
                uint32_t bh0 = *(const uint32_t*)(sm + OFF_B1H + bbyte);
                uint32_t bh1 = *(const uint32_t*)(sm + OFF_B1H + bbyte + 16);
                uint32_t bl0 = *(const uint32_t*)(sm + OFF_B1L + bbyte);
                uint32_t bl1 = *(const uint32_t*)(sm + OFF_B1L + bbyte + 16);
                mma_f16(acc1[j], ah0, ah1, ah2, ah3, bh0, bh1);
                mma_f16(acc1[j], ah0, ah1, ah2, ah3, bl0, bl1);
            }
        }
        __syncthreads();   // X reads done -> region becomes H

        // ---- 3) relu -> H hi (fp16) in smem ----
        #pragma unroll
        for (int j = 0; j < 12; ++j) {
            int N0 = (nh * 12 + j) * 8;
            float c0 = fmaxf(acc1[j][0], 0.f), c1 = fmaxf(acc1[j][1], 0.f);
            float c2 = fmaxf(acc1[j][2], 0.f), c3 = fmaxf(acc1[j][3], 0.f);
            int b0 = (M0 + g) * P192 + (N0 + 2 * t) * 2;
            int b1 = (M0 + g + 8) * P192 + (N0 + 2 * t) * 2;
            *(uint32_t*)(sm + OFF_HH + b0) = pack2(h16(c0), h16(c1));
            *(uint32_t*)(sm + OFF_HH + b1) = pack2(h16(c2), h16(c3));
        }
        __syncthreads();

        // ---- 4) GEMM2: D2(64x96) = Hh @ (B2h + B2l) ----
        float acc2[6][4];
        #pragma unroll
        for (int j = 0; j < 6; ++j)
            #pragma unroll
            for (int p = 0; p < 4; ++p) acc2[j][p] = 0.f;

        #pragma unroll
        for (int ks = 0; ks < 12; ++ks) {
            int abyte = (M0 + g) * P192 + ks * 32 + 4 * t;
            uint32_t ah0 = *(const uint32_t*)(sm + OFF_HH + abyte);
            uint32_t ah1 = *(const uint32_t*)(sm + OFF_HH + abyte + 8 * P192);
            uint32_t ah2 = *(const uint32_t*)(sm + OFF_HH + abyte + 16);
            uint32_t ah3 = *(const uint32_t*)(sm + OFF_HH + abyte + 8 * P192 + 16);
            #pragma unroll
            for (int j = 0; j < 6; ++j) {
                int bbyte = ((nh * 6 + j) * 8 + g) * P192 + ks * 32 + 4 * t;
                uint32_t bh0 = *(const uint32_t*)(sm + OFF_B2H + bbyte);
                uint32_t bh1 = *(const uint32_t*)(sm + OFF_B2H + bbyte + 16);
                uint32_t bl0 = *(const uint32_t*)(sm + OFF_B2L + bbyte);
                uint32_t bl1 = *(const uint32_t*)(sm + OFF_B2L + bbyte + 16);
                mma_f16(acc2[j], ah0, ah1, ah2, ah3, bh0, bh1);
                mma_f16(acc2[j], ah0, ah1, ah2, ah3, bl0, bl1);
            }
        }

        // ---- 5) sigmoid + LayerNorm + x*lr ----
        {
            const int r0 = M0 + g, r1 = M0 + g + 8;
            float v[6][4];
            float p0 = 0.f, p1 = 0.f;
            #pragma unroll
            for (int j = 0; j < 6; ++j) {
                #pragma unroll
                for (int p = 0; p < 4; ++p)
                    v[j][p] = __fdividef(1.f, 1.f + __expf(-acc2[j][p]));
                p0 += v[j][0] + v[j][1];
                p1 += v[j][2] + v[j][3];
            }
            p0 += __shfl_xor_sync(0xffffffffu, p0, 1);
            p0 += __shfl_xor_sync(0xffffffffu, p0, 2);
            p1 += __shfl_xor_sync(0xffffffffu, p1, 1);
            p1 += __shfl_xor_sync(0xffffffffu, p1, 2);
            if (t == 0) { S[nh * 64 + r0] = p0; S[nh * 64 + r1] = p1; }
            __syncthreads();
            float mu0 = (S[r0] + S[64 + r0]) * (1.f / 96.f);
            float mu1 = (S[r1] + S[64 + r1]) * (1.f / 96.f);

            float q0 = 0.f, q1 = 0.f;
            #pragma unroll
            for (int j = 0; j < 6; ++j) {
                float d0 = v[j][0] - mu0, d1 = v[j][1] - mu0;
                float d2 = v[j][2] - mu1, d3 = v[j][3] - mu1;
                q0 += d0 * d0 + d1 * d1;
                q1 += d2 * d2 + d3 * d3;
            }
            q0 += __shfl_xor_sync(0xffffffffu, q0, 1);
            q0 += __shfl_xor_sync(0xffffffffu, q0, 2);
            q1 += __shfl_xor_sync(0xffffffffu, q1, 1);
            q1 += __shfl_xor_sync(0xffffffffu, q1, 2);
            if (t == 0) { Q[nh * 64 + r0] = q0; Q[nh * 64 + r1] = q1; }
            __syncthreads();
            float inv0 = rsqrtf((Q[r0] + Q[64 + r0]) * (1.f / 96.f) + 1e-6f);
            float inv1 = rsqrtf((Q[r1] + Q[64 + r1]) * (1.f / 96.f) + 1e-6f);

            #pragma unroll
            for (int j = 0; j < 6; ++j) {
                int col = (nh * 6 + j) * 8 + 2 * t;
                float2 gmv = *(const float2*)&GAM[col];
                float2 btv = *(const float2*)&BET[col];
                float2 xv0 = *(const float2*)(x + (rowbase + r0) * LDIM + col);
                float2 xv1 = *(const float2*)(x + (rowbase + r1) * LDIM + col);
                float2 o0, o1;
                o0.x = xv0.x * ((v[j][0] - mu0) * inv0 * gmv.x + btv.x);
                o0.y = xv0.y * ((v[j][1] - mu0) * inv0 * gmv.y + btv.y);
                o1.x = xv1.x * ((v[j][2] - mu1) * inv1 * gmv.x + btv.x);
                o1.y = xv1.y * ((v[j][3] - mu1) * inv1 * gmv.y + btv.y);
                *(float2*)(out + (rowbase + r0) * LDIM + col) = o0;
                *(float2*)(out + (rowbase + r1) * LDIM + col) = o1;
            }
        }
        __syncthreads();   // H reads done before next tile's X staging
    }
}

extern "C" void kernel_launch(void* const* d_in, const int* in_sizes, int n_in,
                              void* d_out, int out_size) {
    const float* x     = (const float*)d_in[0];
    const float* W1    = (const float*)d_in[1];
    const float* W2    = (const float*)d_in[2];
    const float* gamma = (const float*)d_in[3];
    const float* beta  = (const float*)d_in[4];
    float* out = (float*)d_out;

    int rows   = in_sizes[0] / LDIM;     // 786432
    int ntiles = rows / TILE_R;          // 12288

    precompute_m1_kernel<<<LDIM, FDIM>>>(W1);

    cudaFuncSetAttribute(fused_mma_kernel,
                         cudaFuncAttributeMaxDynamicSharedMemorySize, SMEM_BYTES);

    int nsm = 148;
    cudaDeviceGetAttribute(&nsm, cudaDevAttrMultiProcessorCount, 0);
    int grid = nsm < ntiles ? nsm : ntiles;

    fused_mma_kernel<<<grid, NTHREADS, SMEM_BYTES>>>(x, W2, gamma, beta, out, ntiles);
}

// round 16
// speedup vs baseline: 1.8368x; 1.2043x over previous
#include <cuda_runtime.h>
#include <cuda_fp16.h>
#include <math.h>
#include <stdint.h>

#define LDIM 96
#define FDIM 192
#define TILE_R 64
#define NTHREADS 256     // 8 warps = 2 m-halves (32 rows) x 4 n-quarters

// pitches conflict-free: P96 = 208 B (k=96), P192 = 400 B (k=192)
#define P96   208
#define P192  400
#define OFF_B1H 0                      // M1 hi: 192 n x 96 k fp16 (39,936)
#define OFF_B1L 39936
#define OFF_B2H 79872                  // W2^T hi: 96 n x 192 k fp16 (38,400)
#define OFF_B2L 118272
#define OFF_XH  156672                 // X hi: 64 x 96 fp16 (13,312)  [aliases H]
#define OFF_HH  156672                 // H hi: 64 x 192 fp16 (25,600)
#define OFF_S   182272                 // 4 x 64 f32 (1,024)
#define OFF_Q   183296                 // 4 x 64 f32 (1,024)
#define OFF_GAM 184320                 // 96 f32
#define OFF_BET 184704                 // 96 f32
#define SMEM_BYTES 185088

// Folded DCT * W1 (96 x 192), fp64 accumulation, recomputed every launch.
__device__ float g_M1[LDIM * FDIM];

__global__ void precompute_m1_kernel(const float* __restrict__ W1) {
    __shared__ double ct[LDIM];
    int n = blockIdx.x;
    int j = threadIdx.x;
    if (j < LDIM) {
        double base = 3.14159265358979323846 * (2.0 * (double)n + 1.0) / (2.0 * (double)LDIM);
        ct[j] = 2.0 * cos(base * (double)j);
    }
    __syncthreads();
    double acc = 0.0;
    for (int f = 0; f < LDIM; ++f)
        acc += ct[f] * (double)W1[f * FDIM + j];
    g_M1[n * FDIM + j] = (float)acc;
}

__device__ __forceinline__ void mma_f16(float* c, uint32_t a0, uint32_t a1,
                                        uint32_t a2, uint32_t a3,
                                        uint32_t b0, uint32_t b1) {
    asm volatile(
        "mma.sync.aligned.m16n8k16.row.col.f32.f16.f16.f32 "
        "{%0,%1,%2,%3}, {%4,%5,%6,%7}, {%8,%9}, {%0,%1,%2,%3};"
        : "+f"(c[0]), "+f"(c[1]), "+f"(c[2]), "+f"(c[3])
        : "r"(a0), "r"(a1), "r"(a2), "r"(a3), "r"(b0), "r"(b1));
}

__device__ __forceinline__ void split1(float v, uint16_t& h, uint16_t& l) {
    __half hb = __float2half_rn(v);
    __half lb = __float2half_rn(v - __half2float(hb));
    h = __half_as_ushort(hb);
    l = __half_as_ushort(lb);
}
__device__ __forceinline__ uint16_t h16(float v) {
    return __half_as_ushort(__float2half_rn(v));
}
__device__ __forceinline__ uint32_t pack2(uint16_t lo, uint16_t hi) {
    return (uint32_t)lo | ((uint32_t)hi << 16);
}

__global__ void __launch_bounds__(NTHREADS, 1)
fused_mma_kernel(const float* __restrict__ x,
                 const float* __restrict__ W2,
                 const float* __restrict__ gamma,
                 const float* __restrict__ beta,
                 float* __restrict__ out,
                 int ntiles)
{
    extern __shared__ char sm[];
    float* S   = (float*)(sm + OFF_S);
    float* Q   = (float*)(sm + OFF_Q);
    float* GAM = (float*)(sm + OFF_GAM);
    float* BET = (float*)(sm + OFF_BET);

    const int tid  = threadIdx.x;
    const int lane = tid & 31;
    const int wid  = tid >> 5;         // 0..7
    const int mh   = wid & 1;          // m-half: rows mh*32 .. mh*32+31
    const int nq   = wid >> 1;         // n-quarter 0..3
    const int g    = lane >> 2;        // 0..7
    const int t    = lane & 3;         // 0..3
    const int M0a  = mh * 32;          // first m16 block
    const int M0b  = mh * 32 + 16;     // second m16 block

    // ---- one-time weight prep: fp16 hi/lo, conflict-free pitches ----
    for (int i = tid; i < LDIM * FDIM; i += NTHREADS) {      // B1[n][k] = M1[k][n]
        int k = i / FDIM, n = i - k * FDIM;
        uint16_t h, l; split1(g_M1[i], h, l);
        *(uint16_t*)(sm + OFF_B1H + n * P96 + k * 2) = h;
        *(uint16_t*)(sm + OFF_B1L + n * P96 + k * 2) = l;
    }
    for (int i = tid; i < FDIM * LDIM; i += NTHREADS) {      // B2[n][k] = W2[k][n]
        int k = i / LDIM, n = i - k * LDIM;
        uint16_t h, l; split1(W2[i], h, l);
        *(uint16_t*)(sm + OFF_B2H + n * P192 + k * 2) = h;
        *(uint16_t*)(sm + OFF_B2L + n * P192 + k * 2) = l;
    }
    if (tid < 96) { GAM[tid] = gamma[tid]; BET[tid] = beta[tid]; }
    __syncthreads();

    // ---- prologue: stage first X tile ----
    if (blockIdx.x < ntiles) {
        const float4* xg = (const float4*)(x + (size_t)blockIdx.x * (TILE_R * LDIM));
        #pragma unroll
        for (int it = 0; it < 6; ++it) {
            int i4 = tid + it * NTHREADS;
            float4 v = xg[i4];
            int e = i4 * 4, r = e / LDIM, c = e - LDIM * r;
            *(uint32_t*)(sm + OFF_XH + r * P96 + c * 2)     = pack2(h16(v.x), h16(v.y));
            *(uint32_t*)(sm + OFF_XH + r * P96 + c * 2 + 4) = pack2(h16(v.z), h16(v.w));
        }
    }
    __syncthreads();

    for (int tile = blockIdx.x; tile < ntiles; tile += gridDim.x) {
        const size_t rowbase = (size_t)tile * TILE_R;

        // ---- 0) prefetch next tile's X into registers (hidden under GEMMs) ----
        const int ntile = tile + gridDim.x;
        const bool havepf = ntile < ntiles;
        float4 pf[6];
        if (havepf) {
            const float4* xg = (const float4*)(x + (size_t)ntile * (TILE_R * LDIM));
            #pragma unroll
            for (int it = 0; it < 6; ++it) pf[it] = xg[tid + it * NTHREADS];
        }

        // ---- 1) GEMM1: D1(64x192) = Xh @ (B1h + B1l); 2 m-blocks x 6 j ----
        float acc1[2][6][4];
        #pragma unroll
        for (int mb = 0; mb < 2; ++mb)
            #pragma unroll
            for (int j = 0; j < 6; ++j)
                #pragma unroll
                for (int p = 0; p < 4; ++p) acc1[mb][j][p] = 0.f;

        #pragma unroll
        for (int ks = 0; ks < 6; ++ks) {
            int abA = (M0a + g) * P96 + ks * 32 + 4 * t;
            int abB = (M0b + g) * P96 + ks * 32 + 4 * t;
            uint32_t a00 = *(const uint32_t*)(sm + OFF_XH + abA);
            uint32_t a01 = *(const uint32_t*)(sm + OFF_XH + abA + 8 * P96);
            uint32_t a02 = *(const uint32_t*)(sm + OFF_XH + abA + 16);
            uint32_t a03 = *(const uint32_t*)(sm + OFF_XH + abA + 8 * P96 + 16);
            uint32_t a10 = *(const uint32_t*)(sm + OFF_XH + abB);
            uint32_t a11 = *(const uint32_t*)(sm + OFF_XH + abB + 8 * P96);
            uint32_t a12 = *(const uint32_t*)(sm + OFF_XH + abB + 16);
            uint32_t a13 = *(const uint32_t*)(sm + OFF_XH + abB + 8 * P96 + 16);
            #pragma unroll
            for (int j = 0; j < 6; ++j) {
                int bbyte = ((nq * 6 + j) * 8 + g) * P96 + ks * 32 + 4 * t;
                uint32_t bh0 = *(const uint32_t*)(sm + OFF_B1H + bbyte);
                uint32_t bh1 = *(const uint32_t*)(sm + OFF_B1H + bbyte + 16);
                uint32_t bl0 = *(const uint32_t*)(sm + OFF_B1L + bbyte);
                uint32_t bl1 = *(const uint32_t*)(sm + OFF_B1L + bbyte + 16);
                mma_f16(acc1[0][j], a00, a01, a02, a03, bh0, bh1);
                mma_f16(acc1[0][j], a00, a01, a02, a03, bl0, bl1);
                mma_f16(acc1[1][j], a10, a11, a12, a13, bh0, bh1);
                mma_f16(acc1[1][j], a10, a11, a12, a13, bl0, bl1);
            }
        }
        __syncthreads();   // X reads done -> region becomes H

        // ---- 2) relu -> H hi (fp16) in smem ----
        #pragma unroll
        for (int mb = 0; mb < 2; ++mb) {
            int M0 = mb ? M0b : M0a;
            #pragma unroll
            for (int j = 0; j < 6; ++j) {
                int N0 = (nq * 6 + j) * 8;
                float c0 = fmaxf(acc1[mb][j][0], 0.f), c1 = fmaxf(acc1[mb][j][1], 0.f);
                float c2 = fmaxf(acc1[mb][j][2], 0.f), c3 = fmaxf(acc1[mb][j][3], 0.f);
                int b0 = (M0 + g) * P192 + (N0 + 2 * t) * 2;
                int b1 = (M0 + g + 8) * P192 + (N0 + 2 * t) * 2;
                *(uint32_t*)(sm + OFF_HH + b0) = pack2(h16(c0), h16(c1));
                *(uint32_t*)(sm + OFF_HH + b1) = pack2(h16(c2), h16(c3));
            }
        }
        __syncthreads();

        // ---- 3) GEMM2: D2(64x96) = Hh @ (B2h + B2l); 2 m-blocks x 3 j ----
        float acc2[2][3][4];
        #pragma unroll
        for (int mb = 0; mb < 2; ++mb)
            #pragma unroll
            for (int j = 0; j < 3; ++j)
                #pragma unroll
                for (int p = 0; p < 4; ++p) acc2[mb][j][p] = 0.f;

        #pragma unroll
        for (int ks = 0; ks < 12; ++ks) {
            int abA = (M0a + g) * P192 + ks * 32 + 4 * t;
            int abB = (M0b + g) * P192 + ks * 32 + 4 * t;
            uint32_t a00 = *(const uint32_t*)(sm + OFF_HH + abA);
            uint32_t a01 = *(const uint32_t*)(sm + OFF_HH + abA + 8 * P192);
            uint32_t a02 = *(const uint32_t*)(sm + OFF_HH + abA + 16);
            uint32_t a03 = *(const uint32_t*)(sm + OFF_HH + abA + 8 * P192 + 16);
            uint32_t a10 = *(const uint32_t*)(sm + OFF_HH + abB);
            uint32_t a11 = *(const uint32_t*)(sm + OFF_HH + abB + 8 * P192);
            uint32_t a12 = *(const uint32_t*)(sm + OFF_HH + abB + 16);
            uint32_t a13 = *(const uint32_t*)(sm + OFF_HH + abB + 8 * P192 + 16);
            #pragma unroll
            for (int j = 0; j < 3; ++j) {
                int bbyte = ((nq * 3 + j) * 8 + g) * P192 + ks * 32 + 4 * t;
                uint32_t bh0 = *(const uint32_t*)(sm + OFF_B2H + bbyte);
                uint32_t bh1 = *(const uint32_t*)(sm + OFF_B2H + bbyte + 16);
                uint32_t bl0 = *(const uint32_t*)(sm + OFF_B2L + bbyte);
                uint32_t bl1 = *(const uint32_t*)(sm + OFF_B2L + bbyte + 16);
                mma_f16(acc2[0][j], a00, a01, a02, a03, bh0, bh1);
                mma_f16(acc2[0][j], a00, a01, a02, a03, bl0, bl1);
                mma_f16(acc2[1][j], a10, a11, a12, a13, bh0, bh1);
                mma_f16(acc2[1][j], a10, a11, a12, a13, bl0, bl1);
            }
        }

        // ---- 4) sigmoid + LayerNorm + x*lr ----
        {
            // rows: [mb=0] r0=M0a+g, r1=M0a+g+8; [mb=1] r2=M0b+g, r3=M0b+g+8
            float v[2][3][4];
            float p[4] = {0.f, 0.f, 0.f, 0.f};
            #pragma unroll
            for (int mb = 0; mb < 2; ++mb)
                #pragma unroll
                for (int j = 0; j < 3; ++j) {
                    #pragma unroll
                    for (int q2 = 0; q2 < 4; ++q2)
                        v[mb][j][q2] = __fdividef(1.f, 1.f + __expf(-acc2[mb][j][q2]));
                    p[mb * 2]     += v[mb][j][0] + v[mb][j][1];
                    p[mb * 2 + 1] += v[mb][j][2] + v[mb][j][3];
                }
            #pragma unroll
            for (int r = 0; r < 4; ++r) {
                p[r] += __shfl_xor_sync(0xffffffffu, p[r], 1);
                p[r] += __shfl_xor_sync(0xffffffffu, p[r], 2);
            }
            int rows[4] = {M0a + g, M0a + g + 8, M0b + g, M0b + g + 8};
            if (t == 0) {
                #pragma unroll
                for (int r = 0; r < 4; ++r) S[nq * 64 + rows[r]] = p[r];
            }
            __syncthreads();
            float mu[4];
            #pragma unroll
            for (int r = 0; r < 4; ++r)
                mu[r] = (S[rows[r]] + S[64 + rows[r]] + S[128 + rows[r]] + S[192 + rows[r]])
                        * (1.f / 96.f);

            float q[4] = {0.f, 0.f, 0.f, 0.f};
            #pragma unroll
            for (int mb = 0; mb < 2; ++mb)
                #pragma unroll
                for (int j = 0; j < 3; ++j) {
                    float d0 = v[mb][j][0] - mu[mb * 2],     d1 = v[mb][j][1] - mu[mb * 2];
                    float d2 = v[mb][j][2] - mu[mb * 2 + 1], d3 = v[mb][j][3] - mu[mb * 2 + 1];
                    q[mb * 2]     += d0 * d0 + d1 * d1;
                    q[mb * 2 + 1] += d2 * d2 + d3 * d3;
                }
            #pragma unroll
            for (int r = 0; r < 4; ++r) {
                q[r] += __shfl_xor_sync(0xffffffffu, q[r], 1);
                q[r] += __shfl_xor_sync(0xffffffffu, q[r], 2);
            }
            if (t == 0) {
                #pragma unroll
                for (int r = 0; r < 4; ++r) Q[nq * 64 + rows[r]] = q[r];
            }
            __syncthreads();   // after this, ALL warps' GEMM2 (H reads) are done
            float inv[4];
            #pragma unroll
            for (int r = 0; r < 4; ++r)
                inv[r] = rsqrtf((Q[rows[r]] + Q[64 + rows[r]] + Q[128 + rows[r]] + Q[192 + rows[r]])
                                * (1.f / 96.f) + 1e-6f);

            #pragma unroll
            for (int mb = 0; mb < 2; ++mb)
                #pragma unroll
                for (int j = 0; j < 3; ++j) {
                    int col = (nq * 3 + j) * 8 + 2 * t;
                    float2 gmv = *(const float2*)&GAM[col];
                    float2 btv = *(const float2*)&BET[col];
                    int ra = rows[mb * 2], rb = rows[mb * 2 + 1];
                    float2 xva = *(const float2*)(x + (rowbase + ra) * LDIM + col);
                    float2 xvb = *(const float2*)(x + (rowbase + rb) * LDIM + col);
                    float2 oa, ob;
                    oa.x = xva.x * ((v[mb][j][0] - mu[mb * 2]) * inv[mb * 2] * gmv.x + btv.x);
                    oa.y = xva.y * ((v[mb][j][1] - mu[mb * 2]) * inv[mb * 2] * gmv.y + btv.y);
                    ob.x = xvb.x * ((v[mb][j][2] - mu[mb * 2 + 1]) * inv[mb * 2 + 1] * gmv.x + btv.x);
                    ob.y = xvb.y * ((v[mb][j][3] - mu[mb * 2 + 1]) * inv[mb * 2 + 1] * gmv.y + btv.y);
                    *(float2*)(out + (rowbase + ra) * LDIM + col) = oa;
                    *(float2*)(out + (rowbase + rb) * LDIM + col) = ob;
                }
        }

        // ---- 5) store prefetched X(t+1) over H (all H reads done at Q-barrier) ----
        if (havepf) {
            #pragma unroll
            for (int it = 0; it < 6; ++it) {
                int i4 = tid + it * NTHREADS;
                int e = i4 * 4, r = e / LDIM, c = e - LDIM * r;
                *(uint32_t*)(sm + OFF_XH + r * P96 + c * 2) =
                    pack2(h16(pf[it].x), h16(pf[it].y));
                *(uint32_t*)(sm + OFF_XH + r * P96 + c * 2 + 4) =
                    pack2(h16(pf[it].z), h16(pf[it].w));
            }
        }
        __syncthreads();   // X(t+1) staged before next GEMM1
    }
}

extern "C" void kernel_launch(void* const* d_in, const int* in_sizes, int n_in,
                              void* d_out, int out_size) {
    const float* x     = (const float*)d_in[0];
    const float* W1    = (const float*)d_in[1];
    const float* W2    = (const float*)d_in[2];
    const float* gamma = (const float*)d_in[3];
    const float* beta  = (const float*)d_in[4];
    float* out = (float*)d_out;

    int rows   = in_sizes[0] / LDIM;     // 786432
    int ntiles = rows / TILE_R;          // 12288

    precompute_m1_kernel<<<LDIM, FDIM>>>(W1);

    cudaFuncSetAttribute(fused_mma_kernel,
                         cudaFuncAttributeMaxDynamicSharedMemorySize, SMEM_BYTES);

    int nsm = 148;
    cudaDeviceGetAttribute(&nsm, cudaDevAttrMultiProcessorCount, 0);
    int grid = nsm < ntiles ? nsm : ntiles;

    fused_mma_kernel<<<grid, NTHREADS, SMEM_BYTES>>>(x, W2, gamma, beta, out, ntiles);
}